// round 4
// baseline (speedup 1.0000x reference)
#include <cuda_runtime.h>
#include <cuda_bf16.h>

#define BATCH   16
#define NPTS    4096
#define DFEAT   64
#define NPOINT  1024
#define NSAMPLE 32
#define P_TOT   (BATCH*NPOINT*NSAMPLE)   // 524288
#define PBLK    (P_TOT/128)              // 4096 row-tiles of 128

typedef unsigned long long u64;

__device__ __forceinline__ u64 pk2(float lo, float hi) {
    u64 r; asm("mov.b64 %0,{%1,%2};" : "=l"(r) : "f"(lo), "f"(hi)); return r;
}
__device__ __forceinline__ void upk2(u64 v, float& lo, float& hi) {
    asm("mov.b64 {%0,%1},%2;" : "=f"(lo), "=f"(hi) : "l"(v));
}
__device__ __forceinline__ u64 fma2(u64 a, u64 b, u64 c) {
    u64 d; asm("fma.rn.f32x2 %0,%1,%2,%3;" : "=l"(d) : "l"(a), "l"(b), "l"(c)); return d;
}

// ---------------- device scratch ----------------
__device__ float g_ptsT[(size_t)BATCH*NPTS*DFEAT];
__device__ float g_xyzT[(size_t)BATCH*NPTS*3];
__device__ float g_newxyz[(size_t)BATCH*NPOINT*3];
__device__ int   g_gidx[(size_t)BATCH*NPOINT*NSAMPLE];
__device__ float g_x1[(size_t)P_TOT*64];
__device__ float g_x2[(size_t)P_TOT*64];
__device__ float g_x3[(size_t)P_TOT*128];
__device__ float g_part[(size_t)2*128*PBLK];
__device__ float g_scale[3*128];
__device__ float g_shift[3*128];

// ---------------- prep: transpose points & xyz ----------------
__global__ void __launch_bounds__(256) prep_kernel(const float* __restrict__ xyz,
                                                   const float* __restrict__ pts) {
    int b = blockIdx.y, n0 = blockIdx.x * 64, tid = threadIdx.x;
    __shared__ float t[64][65];
    const float* src = pts + (size_t)b * DFEAT * NPTS;
#pragma unroll
    for (int j = 0; j < 16; j++) {
        int i = tid + j * 256;
        int c = i >> 6, n = i & 63;
        t[n][c] = src[(size_t)c * NPTS + n0 + n];
    }
    __syncthreads();
    float* dst = g_ptsT + ((size_t)b * NPTS + n0) * DFEAT;
#pragma unroll
    for (int j = 0; j < 16; j++) {
        int i = tid + j * 256;
        int n = i >> 6, c = i & 63;
        dst[i] = t[n][c];
    }
    if (tid < 192) {
        int c = tid / 64, n = tid % 64;
        g_xyzT[((size_t)b * NPTS + n0 + n) * 3 + c] =
            xyz[(size_t)b * 3 * NPTS + (size_t)c * NPTS + n0 + n];
    }
}

// ---------------- FPS: regs + single-barrier double-buffered reduce ---------
__global__ void __launch_bounds__(256) fps_kernel(const float* __restrict__ xyz,
                                                  float* __restrict__ out) {
    int b = blockIdx.x, tid = threadIdx.x;
    int w = tid >> 5, lane = tid & 31;
    __shared__ float sx[NPTS], sy[NPTS], sz[NPTS];
    __shared__ float swv[2][8];
    __shared__ int   swi[2][8];
    const float* base = xyz + (size_t)b * 3 * NPTS;
    for (int i = tid; i < NPTS; i += 256) {
        sx[i] = base[i]; sy[i] = base[NPTS + i]; sz[i] = base[2 * NPTS + i];
    }
    float px[16], py[16], pz[16], dist[16];
#pragma unroll
    for (int j = 0; j < 16; j++) {
        int p = j * 256 + tid;
        px[j] = base[p]; py[j] = base[NPTS + p]; pz[j] = base[2 * NPTS + p];
        dist[j] = 1e10f;
    }
    __syncthreads();
    int far = 0, buf = 0;
    for (int it = 0; it < NPOINT; it++) {
        float cx = sx[far], cy = sy[far], cz = sz[far];
        if (tid == 0) {
            out[(size_t)b * 3 * NPOINT + it]              = cx;
            out[(size_t)b * 3 * NPOINT + NPOINT + it]     = cy;
            out[(size_t)b * 3 * NPOINT + 2 * NPOINT + it] = cz;
            g_newxyz[((size_t)b * NPOINT + it) * 3 + 0] = cx;
            g_newxyz[((size_t)b * NPOINT + it) * 3 + 1] = cy;
            g_newxyz[((size_t)b * NPOINT + it) * 3 + 2] = cz;
        }
        float best = -1.f; int bi = 0;
#pragma unroll
        for (int j = 0; j < 16; j++) {
            float dx = px[j] - cx, dy = py[j] - cy, dz = pz[j] - cz;
            float d = __fadd_rn(__fadd_rn(__fmul_rn(dx, dx), __fmul_rn(dy, dy)), __fmul_rn(dz, dz));
            float dm = fminf(dist[j], d);
            dist[j] = dm;
            if (dm > best) { best = dm; bi = j * 256 + tid; }
        }
#pragma unroll
        for (int o = 16; o; o >>= 1) {
            float ov = __shfl_down_sync(0xffffffffu, best, o);
            int   oi = __shfl_down_sync(0xffffffffu, bi, o);
            if (ov > best || (ov == best && oi < bi)) { best = ov; bi = oi; }
        }
        if (lane == 0) { swv[buf][w] = best; swi[buf][w] = bi; }
        __syncthreads();
        // all warps redundantly reduce the 8 partials (no second barrier)
        float v = lane < 8 ? swv[buf][lane] : -2.f;
        int   ii = lane < 8 ? swi[buf][lane] : 0;
#pragma unroll
        for (int o = 4; o; o >>= 1) {
            float ov = __shfl_down_sync(0xffffffffu, v, o);
            int   oi = __shfl_down_sync(0xffffffffu, ii, o);
            if (ov > v || (ov == v && oi < ii)) { v = ov; ii = oi; }
        }
        far = __shfl_sync(0xffffffffu, ii, 0);
        buf ^= 1;
    }
}

// ---------------- ball query (unchanged numerics) ----------------
__global__ void __launch_bounds__(256) ballq_kernel(const float* __restrict__ xyz) {
    int b = blockIdx.y, tid = threadIdx.x;
    __shared__ float sx[NPTS], sy[NPTS], sz[NPTS];
    const float* base = xyz + (size_t)b * 3 * NPTS;
    for (int i = tid; i < NPTS; i += 256) {
        sx[i] = base[i]; sy[i] = base[NPTS + i]; sz[i] = base[2 * NPTS + i];
    }
    __syncthreads();
    int w = tid >> 5, lane = tid & 31;
    const float R2 = 0.01f;
    for (int ci = 0; ci < 8; ci++) {
        int s = blockIdx.x * 64 + w * 8 + ci;
        const float* cp = g_newxyz + ((size_t)b * NPOINT + s) * 3;
        float cx = cp[0], cy = cp[1], cz = cp[2];
        float s2 = __fadd_rn(__fadd_rn(__fmul_rn(cx, cx), __fmul_rn(cy, cy)), __fmul_rn(cz, cz));
        int cnt = 0, first = 0;
        int* gb = g_gidx + ((size_t)b * NPOINT + s) * NSAMPLE;
        for (int basei = 0; basei < NPTS; basei += 32) {
            int p = basei + lane;
            float x = sx[p], y = sy[p], z = sz[p];
            float p2 = __fadd_rn(__fadd_rn(__fmul_rn(x, x), __fmul_rn(y, y)), __fmul_rn(z, z));
            float dot = x * cx + y * cy + z * cz;
            float d = __fadd_rn(__fadd_rn(__fmul_rn(-2.f, dot), s2), p2);
            bool ok = !(d > R2);
            unsigned m = __ballot_sync(0xffffffffu, ok);
            if (cnt == 0 && m) first = basei + __ffs(m) - 1;
            int r = __popc(m & ((1u << lane) - 1u));
            if (ok && cnt + r < 32) gb[cnt + r] = p;
            cnt += __popc(m);
            if (cnt >= 32) break;
        }
        if (cnt < 32) {
            int j = cnt + lane;
            if (j < 32) gb[j] = first;
        }
    }
}

#define FS_STRIDE 68
#define GET(f4, j) ((j) == 0 ? (f4).x : (j) == 1 ? (f4).y : (j) == 2 ? (f4).z : (f4).w)

// ============ layer 1: gather + GEMM (68-pad K -> 64, f32x2) + stats ========
__global__ void __launch_bounds__(256) l1_kernel(const float* __restrict__ W0,
                                                 const float* __restrict__ b0) {
    extern __shared__ float sm[];
    float* fs = sm;                       // 128 x 68
    float* ws = sm + 128 * FS_STRIDE;     // 68 x 64
    __shared__ float sred[16][64];
    __shared__ float sb[64];
    int tid = threadIdx.x, bx = blockIdx.x;
    int p0 = bx * 128;
    for (int i = tid; i < 64 * 67; i += 256) {
        int c = i / 67, ko = i % 67;
        int kn = ko < 3 ? 64 + ko : ko - 3;
        ws[kn * 64 + c] = W0[i];
    }
    if (tid < 64) { ws[67 * 64 + tid] = 0.f; sb[tid] = b0[tid]; }
    {
        int r = tid >> 1, h = tid & 1;
        int p = p0 + r;
        int bb = p >> 15;
        int s = (p >> 5) & 1023;
        int idx = g_gidx[p];
        const float* pr = g_ptsT + ((size_t)bb * NPTS + idx) * 64 + h * 32;
#pragma unroll
        for (int i = 0; i < 8; i++)
            *(float4*)&fs[r * FS_STRIDE + h * 32 + i * 4] = *(const float4*)(pr + i * 4);
        if (h == 0) {
            const float* xr = g_xyzT + ((size_t)bb * NPTS + idx) * 3;
            const float* nr = g_newxyz + ((size_t)bb * NPOINT + s) * 3;
            fs[r * FS_STRIDE + 64] = xr[0] - nr[0];
            fs[r * FS_STRIDE + 65] = xr[1] - nr[1];
            fs[r * FS_STRIDE + 66] = xr[2] - nr[2];
        } else {
            fs[r * FS_STRIDE + 67] = 0.f;
        }
    }
    __syncthreads();
    int c0 = (tid & 15) * 4, r0 = (tid >> 4) * 8;
    u64 acc[4][4];
#pragma unroll
    for (int rp = 0; rp < 4; rp++)
#pragma unroll
        for (int j = 0; j < 4; j++) acc[rp][j] = pk2(sb[c0 + j], sb[c0 + j]);
    for (int k4 = 0; k4 < 68; k4 += 4) {
        float4 f[8];
#pragma unroll
        for (int i = 0; i < 8; i++) f[i] = *(float4*)&fs[(r0 + i) * FS_STRIDE + k4];
#pragma unroll
        for (int j = 0; j < 4; j++) {
            float4 wv = *(float4*)&ws[(k4 + j) * 64 + c0];
            u64 w0 = pk2(wv.x, wv.x), w1 = pk2(wv.y, wv.y);
            u64 w2 = pk2(wv.z, wv.z), w3 = pk2(wv.w, wv.w);
#pragma unroll
            for (int rp = 0; rp < 4; rp++) {
                u64 fp = pk2(GET(f[2 * rp], j), GET(f[2 * rp + 1], j));
                acc[rp][0] = fma2(fp, w0, acc[rp][0]);
                acc[rp][1] = fma2(fp, w1, acc[rp][1]);
                acc[rp][2] = fma2(fp, w2, acc[rp][2]);
                acc[rp][3] = fma2(fp, w3, acc[rp][3]);
            }
        }
    }
    float a[8][4];
#pragma unroll
    for (int rp = 0; rp < 4; rp++)
#pragma unroll
        for (int j = 0; j < 4; j++) upk2(acc[rp][j], a[2 * rp][j], a[2 * rp + 1][j]);
#pragma unroll
    for (int i = 0; i < 8; i++) {
        float4 o; o.x = a[i][0]; o.y = a[i][1]; o.z = a[i][2]; o.w = a[i][3];
        *(float4*)(g_x1 + (size_t)(p0 + r0 + i) * 64 + c0) = o;
    }
    float ps[4], pq[4];
#pragma unroll
    for (int j = 0; j < 4; j++) {
        float s = 0.f, q = 0.f;
#pragma unroll
        for (int i = 0; i < 8; i++) { s += a[i][j]; q += a[i][j] * a[i][j]; }
        ps[j] = s; pq[j] = q;
    }
    int pg = tid >> 4;
#pragma unroll
    for (int j = 0; j < 4; j++) sred[pg][c0 + j] = ps[j];
    __syncthreads();
    if (tid < 64) {
        float s = 0.f;
#pragma unroll
        for (int g = 0; g < 16; g++) s += sred[g][tid];
        g_part[(size_t)tid * PBLK + bx] = s;
    }
    __syncthreads();
#pragma unroll
    for (int j = 0; j < 4; j++) sred[pg][c0 + j] = pq[j];
    __syncthreads();
    if (tid < 64) {
        float s = 0.f;
#pragma unroll
        for (int g = 0; g < 16; g++) s += sred[g][tid];
        g_part[(size_t)(64 + tid) * PBLK + bx] = s;
    }
}

// ---------------- fold BN stats into affine ----------------
__global__ void __launch_bounds__(256) fold_kernel(const float* __restrict__ gamma,
                                                   const float* __restrict__ beta,
                                                   int ch_tot, int off) {
    int c = blockIdx.x, tid = threadIdx.x;
    __shared__ float sh1[256], sh2[256];
    float s = 0.f, q = 0.f;
    for (int i = tid; i < PBLK; i += 256) {
        s += g_part[(size_t)c * PBLK + i];
        q += g_part[(size_t)(ch_tot + c) * PBLK + i];
    }
    sh1[tid] = s; sh2[tid] = q;
    __syncthreads();
    for (int o = 128; o; o >>= 1) {
        if (tid < o) { sh1[tid] += sh1[tid + o]; sh2[tid] += sh2[tid + o]; }
        __syncthreads();
    }
    if (tid == 0) {
        float n = (float)P_TOT;
        float mu = sh1[0] / n;
        float var = sh2[0] / n - mu * mu;
        float rs = rsqrtf(var + 1e-5f);
        float sc = gamma[c] * rs;
        g_scale[off + c] = sc;
        g_shift[off + c] = fmaf(-mu, sc, beta[c]);
    }
}

// ============ layer2: affine+relu load, 64->64 GEMM (f32x2), stats ==========
__global__ void __launch_bounds__(256) mlp64_kernel(const float* __restrict__ xin,
                                                    const float* __restrict__ W,
                                                    const float* __restrict__ bias,
                                                    int in_off,
                                                    float* __restrict__ xout) {
    extern __shared__ float sm[];
    float* xs = sm;                       // 128 x 68
    float* ws = sm + 128 * FS_STRIDE;     // 64 x 64
    __shared__ float sred[16][64];
    __shared__ float sb[64];
    int tid = threadIdx.x, bx = blockIdx.x;
    int p0 = bx * 128;
    for (int i = tid; i < 64 * 64; i += 256) {
        int c = i >> 6, k = i & 63;
        ws[k * 64 + c] = W[i];
    }
    if (tid < 64) sb[tid] = bias[tid];
    {
        int r = tid >> 1, h = tid & 1;
        const float* src = xin + (size_t)(p0 + r) * 64 + h * 32;
#pragma unroll
        for (int i = 0; i < 8; i++) {
            float4 v = *(const float4*)(src + i * 4);
            int c = h * 32 + i * 4;
            v.x = fmaxf(fmaf(v.x, g_scale[in_off + c + 0], g_shift[in_off + c + 0]), 0.f);
            v.y = fmaxf(fmaf(v.y, g_scale[in_off + c + 1], g_shift[in_off + c + 1]), 0.f);
            v.z = fmaxf(fmaf(v.z, g_scale[in_off + c + 2], g_shift[in_off + c + 2]), 0.f);
            v.w = fmaxf(fmaf(v.w, g_scale[in_off + c + 3], g_shift[in_off + c + 3]), 0.f);
            *(float4*)&xs[r * FS_STRIDE + c] = v;
        }
    }
    __syncthreads();
    int c0 = (tid & 15) * 4, r0 = (tid >> 4) * 8;
    u64 acc[4][4];
#pragma unroll
    for (int rp = 0; rp < 4; rp++)
#pragma unroll
        for (int j = 0; j < 4; j++) acc[rp][j] = pk2(sb[c0 + j], sb[c0 + j]);
    for (int k4 = 0; k4 < 64; k4 += 4) {
        float4 f[8];
#pragma unroll
        for (int i = 0; i < 8; i++) f[i] = *(float4*)&xs[(r0 + i) * FS_STRIDE + k4];
#pragma unroll
        for (int j = 0; j < 4; j++) {
            float4 wv = *(float4*)&ws[(k4 + j) * 64 + c0];
            u64 w0 = pk2(wv.x, wv.x), w1 = pk2(wv.y, wv.y);
            u64 w2 = pk2(wv.z, wv.z), w3 = pk2(wv.w, wv.w);
#pragma unroll
            for (int rp = 0; rp < 4; rp++) {
                u64 fp = pk2(GET(f[2 * rp], j), GET(f[2 * rp + 1], j));
                acc[rp][0] = fma2(fp, w0, acc[rp][0]);
                acc[rp][1] = fma2(fp, w1, acc[rp][1]);
                acc[rp][2] = fma2(fp, w2, acc[rp][2]);
                acc[rp][3] = fma2(fp, w3, acc[rp][3]);
            }
        }
    }
    float a[8][4];
#pragma unroll
    for (int rp = 0; rp < 4; rp++)
#pragma unroll
        for (int j = 0; j < 4; j++) upk2(acc[rp][j], a[2 * rp][j], a[2 * rp + 1][j]);
#pragma unroll
    for (int i = 0; i < 8; i++) {
        float4 o; o.x = a[i][0]; o.y = a[i][1]; o.z = a[i][2]; o.w = a[i][3];
        *(float4*)(xout + (size_t)(p0 + r0 + i) * 64 + c0) = o;
    }
    float ps[4], pq[4];
#pragma unroll
    for (int j = 0; j < 4; j++) {
        float s = 0.f, q = 0.f;
#pragma unroll
        for (int i = 0; i < 8; i++) { s += a[i][j]; q += a[i][j] * a[i][j]; }
        ps[j] = s; pq[j] = q;
    }
    int pg = tid >> 4;
#pragma unroll
    for (int j = 0; j < 4; j++) sred[pg][c0 + j] = ps[j];
    __syncthreads();
    if (tid < 64) {
        float s = 0.f;
#pragma unroll
        for (int g = 0; g < 16; g++) s += sred[g][tid];
        g_part[(size_t)tid * PBLK + bx] = s;
    }
    __syncthreads();
#pragma unroll
    for (int j = 0; j < 4; j++) sred[pg][c0 + j] = pq[j];
    __syncthreads();
    if (tid < 64) {
        float s = 0.f;
#pragma unroll
        for (int g = 0; g < 16; g++) s += sred[g][tid];
        g_part[(size_t)(64 + tid) * PBLK + bx] = s;
    }
}

// ============ layer3: affine+relu load, 64->128 GEMM (f32x2), stats =========
__global__ void __launch_bounds__(256) mlp128_kernel(const float* __restrict__ xin,
                                                     const float* __restrict__ W,
                                                     const float* __restrict__ bias,
                                                     int in_off,
                                                     float* __restrict__ xout) {
    extern __shared__ float sm[];
    float* xs = sm;                       // 128 x 68
    float* ws = sm + 128 * FS_STRIDE;     // 64 x 128
    __shared__ float sred[16][128];
    __shared__ float sb[128];
    int tid = threadIdx.x, bx = blockIdx.x;
    int p0 = bx * 128;
    for (int i = tid; i < 128 * 64; i += 256) {
        int c = i >> 6, k = i & 63;
        ws[k * 128 + c] = W[i];
    }
    if (tid < 128) sb[tid] = bias[tid];
    {
        int r = tid >> 1, h = tid & 1;
        const float* src = xin + (size_t)(p0 + r) * 64 + h * 32;
#pragma unroll
        for (int i = 0; i < 8; i++) {
            float4 v = *(const float4*)(src + i * 4);
            int c = h * 32 + i * 4;
            v.x = fmaxf(fmaf(v.x, g_scale[in_off + c + 0], g_shift[in_off + c + 0]), 0.f);
            v.y = fmaxf(fmaf(v.y, g_scale[in_off + c + 1], g_shift[in_off + c + 1]), 0.f);
            v.z = fmaxf(fmaf(v.z, g_scale[in_off + c + 2], g_shift[in_off + c + 2]), 0.f);
            v.w = fmaxf(fmaf(v.w, g_scale[in_off + c + 3], g_shift[in_off + c + 3]), 0.f);
            *(float4*)&xs[r * FS_STRIDE + c] = v;
        }
    }
    __syncthreads();
    int c0 = (tid & 15) * 4, r0 = (tid >> 4) * 8;
    u64 acc[4][8];   // [row-pair][col j: 0..3 -> c0+j, 4..7 -> c0+64+j]
#pragma unroll
    for (int rp = 0; rp < 4; rp++)
#pragma unroll
        for (int j = 0; j < 4; j++) {
            acc[rp][j]     = pk2(sb[c0 + j], sb[c0 + j]);
            acc[rp][j + 4] = pk2(sb[c0 + 64 + j], sb[c0 + 64 + j]);
        }
    for (int k4 = 0; k4 < 64; k4 += 4) {
        float4 f[8];
#pragma unroll
        for (int i = 0; i < 8; i++) f[i] = *(float4*)&xs[(r0 + i) * FS_STRIDE + k4];
#pragma unroll
        for (int j = 0; j < 4; j++) {
            float4 wa = *(float4*)&ws[(k4 + j) * 128 + c0];
            float4 wb = *(float4*)&ws[(k4 + j) * 128 + c0 + 64];
            u64 w0 = pk2(wa.x, wa.x), w1 = pk2(wa.y, wa.y);
            u64 w2 = pk2(wa.z, wa.z), w3 = pk2(wa.w, wa.w);
            u64 w4 = pk2(wb.x, wb.x), w5 = pk2(wb.y, wb.y);
            u64 w6 = pk2(wb.z, wb.z), w7 = pk2(wb.w, wb.w);
#pragma unroll
            for (int rp = 0; rp < 4; rp++) {
                u64 fp = pk2(GET(f[2 * rp], j), GET(f[2 * rp + 1], j));
                acc[rp][0] = fma2(fp, w0, acc[rp][0]);
                acc[rp][1] = fma2(fp, w1, acc[rp][1]);
                acc[rp][2] = fma2(fp, w2, acc[rp][2]);
                acc[rp][3] = fma2(fp, w3, acc[rp][3]);
                acc[rp][4] = fma2(fp, w4, acc[rp][4]);
                acc[rp][5] = fma2(fp, w5, acc[rp][5]);
                acc[rp][6] = fma2(fp, w6, acc[rp][6]);
                acc[rp][7] = fma2(fp, w7, acc[rp][7]);
            }
        }
    }
    float a[8][8];
#pragma unroll
    for (int rp = 0; rp < 4; rp++)
#pragma unroll
        for (int j = 0; j < 8; j++) upk2(acc[rp][j], a[2 * rp][j], a[2 * rp + 1][j]);
#pragma unroll
    for (int i = 0; i < 8; i++) {
        float4 o0, o1;
        o0.x = a[i][0]; o0.y = a[i][1]; o0.z = a[i][2]; o0.w = a[i][3];
        o1.x = a[i][4]; o1.y = a[i][5]; o1.z = a[i][6]; o1.w = a[i][7];
        *(float4*)(xout + (size_t)(p0 + r0 + i) * 128 + c0)      = o0;
        *(float4*)(xout + (size_t)(p0 + r0 + i) * 128 + c0 + 64) = o1;
    }
    float ps[8], pq[8];
#pragma unroll
    for (int j = 0; j < 8; j++) {
        float s = 0.f, q = 0.f;
#pragma unroll
        for (int i = 0; i < 8; i++) { s += a[i][j]; q += a[i][j] * a[i][j]; }
        ps[j] = s; pq[j] = q;
    }
    int pg = tid >> 4;
#pragma unroll
    for (int j = 0; j < 4; j++) {
        sred[pg][c0 + j]      = ps[j];
        sred[pg][c0 + 64 + j] = ps[j + 4];
    }
    __syncthreads();
    if (tid < 128) {
        float s = 0.f;
#pragma unroll
        for (int g = 0; g < 16; g++) s += sred[g][tid];
        g_part[(size_t)tid * PBLK + bx] = s;
    }
    __syncthreads();
#pragma unroll
    for (int j = 0; j < 4; j++) {
        sred[pg][c0 + j]      = pq[j];
        sred[pg][c0 + 64 + j] = pq[j + 4];
    }
    __syncthreads();
    if (tid < 128) {
        float s = 0.f;
#pragma unroll
        for (int g = 0; g < 16; g++) s += sred[g][tid];
        g_part[(size_t)(128 + tid) * PBLK + bx] = s;
    }
}

// ---------------- final BN + ReLU + maxpool over K ----------------
__global__ void __launch_bounds__(128) maxpool_kernel(float* __restrict__ out2) {
    int g0 = blockIdx.x * 16, tid = threadIdx.x;
    float sc = g_scale[256 + tid], sh = g_shift[256 + tid];
    float m[16];
#pragma unroll
    for (int gi = 0; gi < 16; gi++) {
        size_t prow = (size_t)(g0 + gi) * 32;
        float mm = 0.f;
#pragma unroll 8
        for (int k = 0; k < 32; k++) {
            float v = g_x3[(prow + k) * 128 + tid];
            mm = fmaxf(mm, fmaxf(fmaf(v, sc, sh), 0.f));
        }
        m[gi] = mm;
    }
    int b = g0 >> 10;
    int s0 = g0 & 1023;
    float* dst = out2 + ((size_t)b * 128 + tid) * NPOINT + s0;
#pragma unroll
    for (int i = 0; i < 4; i++) {
        float4 o; o.x = m[i * 4]; o.y = m[i * 4 + 1]; o.z = m[i * 4 + 2]; o.w = m[i * 4 + 3];
        *(float4*)(dst + i * 4) = o;
    }
}

// ---------------- launch ----------------
extern "C" void kernel_launch(void* const* d_in, const int* in_sizes, int n_in,
                              void* d_out, int out_size) {
    const float* xyz = (const float*)d_in[0];
    const float* pts = (const float*)d_in[1];
    const float* W0 = (const float*)d_in[2];  const float* b0 = (const float*)d_in[3];
    const float* ga0 = (const float*)d_in[4]; const float* be0 = (const float*)d_in[5];
    const float* W1 = (const float*)d_in[6];  const float* b1 = (const float*)d_in[7];
    const float* ga1 = (const float*)d_in[8]; const float* be1 = (const float*)d_in[9];
    const float* W2 = (const float*)d_in[10]; const float* b2 = (const float*)d_in[11];
    const float* ga2 = (const float*)d_in[12]; const float* be2 = (const float*)d_in[13];
    float* out = (float*)d_out;
    float* out2 = out + (size_t)BATCH * 3 * NPOINT;

    float* d_x1; cudaGetSymbolAddress((void**)&d_x1, g_x1);
    float* d_x2; cudaGetSymbolAddress((void**)&d_x2, g_x2);
    float* d_x3; cudaGetSymbolAddress((void**)&d_x3, g_x3);

    const int smem_l1   = (128 * FS_STRIDE + 68 * 64) * 4;
    const int smem_m64  = (128 * FS_STRIDE + 64 * 64) * 4;
    const int smem_m128 = (128 * FS_STRIDE + 64 * 128) * 4;
    cudaFuncSetAttribute(l1_kernel,     cudaFuncAttributeMaxDynamicSharedMemorySize, smem_l1);
    cudaFuncSetAttribute(mlp64_kernel,  cudaFuncAttributeMaxDynamicSharedMemorySize, smem_m64);
    cudaFuncSetAttribute(mlp128_kernel, cudaFuncAttributeMaxDynamicSharedMemorySize, smem_m128);

    prep_kernel<<<dim3(64, 16), 256>>>(xyz, pts);
    fps_kernel<<<16, 256>>>(xyz, out);
    ballq_kernel<<<dim3(16, 16), 256>>>(xyz);

    l1_kernel<<<PBLK, 256, smem_l1>>>(W0, b0);
    fold_kernel<<<64, 256>>>(ga0, be0, 64, 0);

    mlp64_kernel<<<PBLK, 256, smem_m64>>>(d_x1, W1, b1, 0, d_x2);
    fold_kernel<<<64, 256>>>(ga1, be1, 64, 128);

    mlp128_kernel<<<PBLK, 256, smem_m128>>>(d_x2, W2, b2, 128, d_x3);
    fold_kernel<<<128, 256>>>(ga2, be2, 128, 256);

    maxpool_kernel<<<BATCH * NPOINT / 16, 128>>>(out2);
}

// round 10
// speedup vs baseline: 1.8544x; 1.8544x over previous
#include <cuda_runtime.h>
#include <cuda_bf16.h>

#define BATCH   16
#define NPTS    4096
#define DFEAT   64
#define NPOINT  1024
#define NSAMPLE 32
#define P_TOT   (BATCH*NPOINT*NSAMPLE)   // 524288
#define PBLK    (P_TOT/128)              // 4096 row-tiles of 128

typedef unsigned long long u64;

// ---------------- device scratch ----------------
__device__ float g_ptsT[(size_t)BATCH*NPTS*DFEAT];
__device__ float g_xyzT[(size_t)BATCH*NPTS*3];
__device__ float g_newxyz[(size_t)BATCH*NPOINT*3];
__device__ int   g_gidx[(size_t)BATCH*NPOINT*NSAMPLE];
__device__ float g_x1[(size_t)P_TOT*64];
__device__ float g_x2[(size_t)P_TOT*64];
__device__ float g_x3[(size_t)P_TOT*128];
__device__ float g_part[(size_t)2*128*PBLK];
__device__ float g_scale[3*128];
__device__ float g_shift[3*128];

// ---------------- prep: transpose points & xyz ----------------
__global__ void __launch_bounds__(256) prep_kernel(const float* __restrict__ xyz,
                                                   const float* __restrict__ pts) {
    int b = blockIdx.y, n0 = blockIdx.x * 64, tid = threadIdx.x;
    __shared__ float t[64][65];
    const float* src = pts + (size_t)b * DFEAT * NPTS;
#pragma unroll
    for (int j = 0; j < 16; j++) {
        int i = tid + j * 256;
        int c = i >> 6, n = i & 63;
        t[n][c] = src[(size_t)c * NPTS + n0 + n];
    }
    __syncthreads();
    float* dst = g_ptsT + ((size_t)b * NPTS + n0) * DFEAT;
#pragma unroll
    for (int j = 0; j < 16; j++) {
        int i = tid + j * 256;
        int n = i >> 6, c = i & 63;
        dst[i] = t[n][c];
    }
    if (tid < 192) {
        int c = tid / 64, n = tid % 64;
        g_xyzT[((size_t)b * NPTS + n0 + n) * 3 + c] =
            xyz[(size_t)b * 3 * NPTS + (size_t)c * NPTS + n0 + n];
    }
}

// ---------------- FPS: redux warp stage + packed-u64 block stage ------------
__global__ void __launch_bounds__(256) fps_kernel(const float* __restrict__ xyz,
                                                  float* __restrict__ out) {
    int b = blockIdx.x, tid = threadIdx.x;
    int w = tid >> 5, lane = tid & 31;
    __shared__ float sx[NPTS], sy[NPTS], sz[NPTS];
    __shared__ u64 spk[2][8];
    const float* base = xyz + (size_t)b * 3 * NPTS;
    for (int i = tid; i < NPTS; i += 256) {
        sx[i] = base[i]; sy[i] = base[NPTS + i]; sz[i] = base[2 * NPTS + i];
    }
    float px[16], py[16], pz[16], dist[16];
#pragma unroll
    for (int j = 0; j < 16; j++) {
        int p = j * 256 + tid;
        px[j] = base[p]; py[j] = base[NPTS + p]; pz[j] = base[2 * NPTS + p];
        dist[j] = 1e10f;
    }
    __syncthreads();
    int far = 0, buf = 0;
    for (int it = 0; it < NPOINT; it++) {
        float cx = sx[far], cy = sy[far], cz = sz[far];
        if (tid == 0) {
            out[(size_t)b * 3 * NPOINT + it]              = cx;
            out[(size_t)b * 3 * NPOINT + NPOINT + it]     = cy;
            out[(size_t)b * 3 * NPOINT + 2 * NPOINT + it] = cz;
            g_newxyz[((size_t)b * NPOINT + it) * 3 + 0] = cx;
            g_newxyz[((size_t)b * NPOINT + it) * 3 + 1] = cy;
            g_newxyz[((size_t)b * NPOINT + it) * 3 + 2] = cz;
        }
        float best = -1.f; int bi = 0;
#pragma unroll
        for (int j = 0; j < 16; j++) {
            float dx = px[j] - cx, dy = py[j] - cy, dz = pz[j] - cz;
            float d = __fadd_rn(__fadd_rn(__fmul_rn(dx, dx), __fmul_rn(dy, dy)), __fmul_rn(dz, dz));
            float dm = fminf(dist[j], d);
            dist[j] = dm;
            if (dm > best) { best = dm; bi = j * 256 + tid; }
        }
        // warp stage: max value, then min index among maxima (same tie rule)
        unsigned db = __float_as_uint(best);                 // best >= 0 -> monotone
        unsigned m  = __reduce_max_sync(0xffffffffu, db);
        unsigned cand = (db == m) ? (unsigned)bi : 0xffffffffu;
        unsigned bimin = __reduce_min_sync(0xffffffffu, cand);
        if (lane == 0)
            spk[buf][w] = ((u64)m << 32) | (u64)(0xffffffffu - bimin);
        __syncthreads();
        // block stage: every thread reduces all 8 packed values locally
        u64 bp = spk[buf][0];
#pragma unroll
        for (int i = 1; i < 8; i++) { u64 v = spk[buf][i]; if (v > bp) bp = v; }
        far = (int)(0xffffffffu - (unsigned)(bp & 0xffffffffu));
        buf ^= 1;
    }
}

// ---------------- ball query (unchanged numerics) ----------------
__global__ void __launch_bounds__(256) ballq_kernel(const float* __restrict__ xyz) {
    int b = blockIdx.y, tid = threadIdx.x;
    __shared__ float sx[NPTS], sy[NPTS], sz[NPTS];
    const float* base = xyz + (size_t)b * 3 * NPTS;
    for (int i = tid; i < NPTS; i += 256) {
        sx[i] = base[i]; sy[i] = base[NPTS + i]; sz[i] = base[2 * NPTS + i];
    }
    __syncthreads();
    int w = tid >> 5, lane = tid & 31;
    const float R2 = 0.01f;
    for (int ci = 0; ci < 8; ci++) {
        int s = blockIdx.x * 64 + w * 8 + ci;
        const float* cp = g_newxyz + ((size_t)b * NPOINT + s) * 3;
        float cx = cp[0], cy = cp[1], cz = cp[2];
        float s2 = __fadd_rn(__fadd_rn(__fmul_rn(cx, cx), __fmul_rn(cy, cy)), __fmul_rn(cz, cz));
        int cnt = 0, first = 0;
        int* gb = g_gidx + ((size_t)b * NPOINT + s) * NSAMPLE;
        for (int basei = 0; basei < NPTS; basei += 32) {
            int p = basei + lane;
            float x = sx[p], y = sy[p], z = sz[p];
            float p2 = __fadd_rn(__fadd_rn(__fmul_rn(x, x), __fmul_rn(y, y)), __fmul_rn(z, z));
            float dot = x * cx + y * cy + z * cz;
            float d = __fadd_rn(__fadd_rn(__fmul_rn(-2.f, dot), s2), p2);
            bool ok = !(d > R2);
            unsigned m = __ballot_sync(0xffffffffu, ok);
            if (cnt == 0 && m) first = basei + __ffs(m) - 1;
            int r = __popc(m & ((1u << lane) - 1u));
            if (ok && cnt + r < 32) gb[cnt + r] = p;
            cnt += __popc(m);
            if (cnt >= 32) break;
        }
        if (cnt < 32) {
            int j = cnt + lane;
            if (j < 32) gb[j] = first;
        }
    }
}

// ============ layer 1: gather + GEMM k-major (68 -> 64) + stats ============
// fsT[k][row]: k 0..63 = point feats, 64..66 = xyz diff, 67 = zero pad
__global__ void __launch_bounds__(128) l1_kernel(const float* __restrict__ W0,
                                                 const float* __restrict__ b0) {
    extern __shared__ float sm[];
    float* fsT = sm;                  // 68 x 128
    float* ws  = sm + 68 * 128;       // 68 x 64  (k-major)
    __shared__ float sred[16][64];
    __shared__ float sb[64];
    int tid = threadIdx.x, bx = blockIdx.x;
    int p0 = bx * 128;
    for (int i = tid; i < 64 * 67; i += 128) {
        int c = i / 67, ko = i % 67;
        int kn = ko < 3 ? 64 + ko : ko - 3;
        ws[kn * 64 + c] = W0[i];
    }
    if (tid < 64) { ws[67 * 64 + tid] = 0.f; sb[tid] = b0[tid]; }
    {
        int r = tid;
        int p = p0 + r;
        int bb = p >> 15;
        int s = (p >> 5) & 1023;
        int idx = g_gidx[p];
        const float* pr = g_ptsT + ((size_t)bb * NPTS + idx) * 64;
#pragma unroll
        for (int c4 = 0; c4 < 16; c4++) {
            float4 v = *(const float4*)(pr + c4 * 4);
            fsT[(c4 * 4 + 0) * 128 + r] = v.x;
            fsT[(c4 * 4 + 1) * 128 + r] = v.y;
            fsT[(c4 * 4 + 2) * 128 + r] = v.z;
            fsT[(c4 * 4 + 3) * 128 + r] = v.w;
        }
        const float* xr = g_xyzT + ((size_t)bb * NPTS + idx) * 3;
        const float* nr = g_newxyz + ((size_t)bb * NPOINT + s) * 3;
        fsT[64 * 128 + r] = xr[0] - nr[0];
        fsT[65 * 128 + r] = xr[1] - nr[1];
        fsT[66 * 128 + r] = xr[2] - nr[2];
        fsT[67 * 128 + r] = 0.f;
    }
    __syncthreads();
    int c0 = (tid & 7) * 8, r0 = (tid >> 3) * 8;
    float acc[8][8];
#pragma unroll
    for (int i = 0; i < 8; i++)
#pragma unroll
        for (int j = 0; j < 8; j++) acc[i][j] = sb[c0 + j];
#pragma unroll 4
    for (int k = 0; k < 68; k++) {
        float4 fa = *(float4*)&fsT[k * 128 + r0];
        float4 fb = *(float4*)&fsT[k * 128 + r0 + 4];
        float4 wa = *(float4*)&ws[k * 64 + c0];
        float4 wb = *(float4*)&ws[k * 64 + c0 + 4];
        float fr[8] = {fa.x, fa.y, fa.z, fa.w, fb.x, fb.y, fb.z, fb.w};
        float wc[8] = {wa.x, wa.y, wa.z, wa.w, wb.x, wb.y, wb.z, wb.w};
#pragma unroll
        for (int i = 0; i < 8; i++)
#pragma unroll
            for (int j = 0; j < 8; j++)
                acc[i][j] = fmaf(fr[i], wc[j], acc[i][j]);
    }
#pragma unroll
    for (int i = 0; i < 8; i++) {
        float4 o0, o1;
        o0.x = acc[i][0]; o0.y = acc[i][1]; o0.z = acc[i][2]; o0.w = acc[i][3];
        o1.x = acc[i][4]; o1.y = acc[i][5]; o1.z = acc[i][6]; o1.w = acc[i][7];
        *(float4*)(g_x1 + (size_t)(p0 + r0 + i) * 64 + c0)     = o0;
        *(float4*)(g_x1 + (size_t)(p0 + r0 + i) * 64 + c0 + 4) = o1;
    }
    float ps[8], pq[8];
#pragma unroll
    for (int j = 0; j < 8; j++) {
        float s = 0.f, q = 0.f;
#pragma unroll
        for (int i = 0; i < 8; i++) { s += acc[i][j]; q += acc[i][j] * acc[i][j]; }
        ps[j] = s; pq[j] = q;
    }
    int pg = tid >> 3;
#pragma unroll
    for (int j = 0; j < 8; j++) sred[pg][c0 + j] = ps[j];
    __syncthreads();
    if (tid < 64) {
        float s = 0.f;
#pragma unroll
        for (int g = 0; g < 16; g++) s += sred[g][tid];
        g_part[(size_t)tid * PBLK + bx] = s;
    }
    __syncthreads();
#pragma unroll
    for (int j = 0; j < 8; j++) sred[pg][c0 + j] = pq[j];
    __syncthreads();
    if (tid < 64) {
        float s = 0.f;
#pragma unroll
        for (int g = 0; g < 16; g++) s += sred[g][tid];
        g_part[(size_t)(64 + tid) * PBLK + bx] = s;
    }
}

// ---------------- fold BN stats into affine ----------------
__global__ void __launch_bounds__(256) fold_kernel(const float* __restrict__ gamma,
                                                   const float* __restrict__ beta,
                                                   int ch_tot, int off) {
    int c = blockIdx.x, tid = threadIdx.x;
    __shared__ float sh1[256], sh2[256];
    float s = 0.f, q = 0.f;
    for (int i = tid; i < PBLK; i += 256) {
        s += g_part[(size_t)c * PBLK + i];
        q += g_part[(size_t)(ch_tot + c) * PBLK + i];
    }
    sh1[tid] = s; sh2[tid] = q;
    __syncthreads();
    for (int o = 128; o; o >>= 1) {
        if (tid < o) { sh1[tid] += sh1[tid + o]; sh2[tid] += sh2[tid + o]; }
        __syncthreads();
    }
    if (tid == 0) {
        float n = (float)P_TOT;
        float mu = sh1[0] / n;
        float var = sh2[0] / n - mu * mu;
        float rs = rsqrtf(var + 1e-5f);
        float sc = gamma[c] * rs;
        g_scale[off + c] = sc;
        g_shift[off + c] = fmaf(-mu, sc, beta[c]);
    }
}

// ============ layer2: affine+relu load, 64->64 GEMM k-major, stats ==========
__global__ void __launch_bounds__(128) mlp64_kernel(const float* __restrict__ xin,
                                                    const float* __restrict__ W,
                                                    const float* __restrict__ bias,
                                                    int in_off,
                                                    float* __restrict__ xout) {
    extern __shared__ float sm[];
    float* xsT = sm;                  // 64 x 128
    float* ws  = sm + 64 * 128;       // 64 x 64
    __shared__ float sred[16][64];
    __shared__ float sb[64];
    int tid = threadIdx.x, bx = blockIdx.x;
    int p0 = bx * 128;
    for (int i = tid; i < 64 * 64; i += 128) {
        int c = i >> 6, k = i & 63;
        ws[k * 64 + c] = W[i];
    }
    if (tid < 64) sb[tid] = bias[tid];
    {
        int r = tid;
        const float* src = xin + (size_t)(p0 + r) * 64;
#pragma unroll
        for (int c4 = 0; c4 < 16; c4++) {
            float4 v = *(const float4*)(src + c4 * 4);
            int c = c4 * 4;
            v.x = fmaxf(fmaf(v.x, g_scale[in_off + c + 0], g_shift[in_off + c + 0]), 0.f);
            v.y = fmaxf(fmaf(v.y, g_scale[in_off + c + 1], g_shift[in_off + c + 1]), 0.f);
            v.z = fmaxf(fmaf(v.z, g_scale[in_off + c + 2], g_shift[in_off + c + 2]), 0.f);
            v.w = fmaxf(fmaf(v.w, g_scale[in_off + c + 3], g_shift[in_off + c + 3]), 0.f);
            xsT[(c + 0) * 128 + r] = v.x;
            xsT[(c + 1) * 128 + r] = v.y;
            xsT[(c + 2) * 128 + r] = v.z;
            xsT[(c + 3) * 128 + r] = v.w;
        }
    }
    __syncthreads();
    int c0 = (tid & 7) * 8, r0 = (tid >> 3) * 8;
    float acc[8][8];
#pragma unroll
    for (int i = 0; i < 8; i++)
#pragma unroll
        for (int j = 0; j < 8; j++) acc[i][j] = sb[c0 + j];
#pragma unroll 4
    for (int k = 0; k < 64; k++) {
        float4 fa = *(float4*)&xsT[k * 128 + r0];
        float4 fb = *(float4*)&xsT[k * 128 + r0 + 4];
        float4 wa = *(float4*)&ws[k * 64 + c0];
        float4 wb = *(float4*)&ws[k * 64 + c0 + 4];
        float fr[8] = {fa.x, fa.y, fa.z, fa.w, fb.x, fb.y, fb.z, fb.w};
        float wc[8] = {wa.x, wa.y, wa.z, wa.w, wb.x, wb.y, wb.z, wb.w};
#pragma unroll
        for (int i = 0; i < 8; i++)
#pragma unroll
            for (int j = 0; j < 8; j++)
                acc[i][j] = fmaf(fr[i], wc[j], acc[i][j]);
    }
#pragma unroll
    for (int i = 0; i < 8; i++) {
        float4 o0, o1;
        o0.x = acc[i][0]; o0.y = acc[i][1]; o0.z = acc[i][2]; o0.w = acc[i][3];
        o1.x = acc[i][4]; o1.y = acc[i][5]; o1.z = acc[i][6]; o1.w = acc[i][7];
        *(float4*)(xout + (size_t)(p0 + r0 + i) * 64 + c0)     = o0;
        *(float4*)(xout + (size_t)(p0 + r0 + i) * 64 + c0 + 4) = o1;
    }
    float ps[8], pq[8];
#pragma unroll
    for (int j = 0; j < 8; j++) {
        float s = 0.f, q = 0.f;
#pragma unroll
        for (int i = 0; i < 8; i++) { s += acc[i][j]; q += acc[i][j] * acc[i][j]; }
        ps[j] = s; pq[j] = q;
    }
    int pg = tid >> 3;
#pragma unroll
    for (int j = 0; j < 8; j++) sred[pg][c0 + j] = ps[j];
    __syncthreads();
    if (tid < 64) {
        float s = 0.f;
#pragma unroll
        for (int g = 0; g < 16; g++) s += sred[g][tid];
        g_part[(size_t)tid * PBLK + bx] = s;
    }
    __syncthreads();
#pragma unroll
    for (int j = 0; j < 8; j++) sred[pg][c0 + j] = pq[j];
    __syncthreads();
    if (tid < 64) {
        float s = 0.f;
#pragma unroll
        for (int g = 0; g < 16; g++) s += sred[g][tid];
        g_part[(size_t)(64 + tid) * PBLK + bx] = s;
    }
}

// ============ layer3: affine+relu load, 64->128 GEMM k-major, stats =========
__global__ void __launch_bounds__(256) mlp128_kernel(const float* __restrict__ xin,
                                                     const float* __restrict__ W,
                                                     const float* __restrict__ bias,
                                                     int in_off,
                                                     float* __restrict__ xout) {
    extern __shared__ float sm[];
    float* xsT = sm;                  // 64 x 128
    float* ws  = sm + 64 * 128;       // 64 x 128
    __shared__ float sred[16][128];
    __shared__ float sb[128];
    int tid = threadIdx.x, bx = blockIdx.x;
    int p0 = bx * 128;
    for (int i = tid; i < 128 * 64; i += 256) {
        int c = i >> 6, k = i & 63;
        ws[k * 128 + c] = W[i];
    }
    if (tid < 128) sb[tid] = bias[tid];
    {
        int r = tid >> 1, h = tid & 1;
        const float* src = xin + (size_t)(p0 + r) * 64 + h * 32;
#pragma unroll
        for (int c4 = 0; c4 < 8; c4++) {
            float4 v = *(const float4*)(src + c4 * 4);
            int c = h * 32 + c4 * 4;
            v.x = fmaxf(fmaf(v.x, g_scale[in_off + c + 0], g_shift[in_off + c + 0]), 0.f);
            v.y = fmaxf(fmaf(v.y, g_scale[in_off + c + 1], g_shift[in_off + c + 1]), 0.f);
            v.z = fmaxf(fmaf(v.z, g_scale[in_off + c + 2], g_shift[in_off + c + 2]), 0.f);
            v.w = fmaxf(fmaf(v.w, g_scale[in_off + c + 3], g_shift[in_off + c + 3]), 0.f);
            xsT[(c + 0) * 128 + r] = v.x;
            xsT[(c + 1) * 128 + r] = v.y;
            xsT[(c + 2) * 128 + r] = v.z;
            xsT[(c + 3) * 128 + r] = v.w;
        }
    }
    __syncthreads();
    int c0 = (tid & 15) * 4, r0 = (tid >> 4) * 8;
    float acc[8][8];   // cols c0..c0+3 and c0+64..c0+67
#pragma unroll
    for (int i = 0; i < 8; i++)
#pragma unroll
        for (int j = 0; j < 4; j++) {
            acc[i][j]     = sb[c0 + j];
            acc[i][j + 4] = sb[c0 + 64 + j];
        }
#pragma unroll 4
    for (int k = 0; k < 64; k++) {
        float4 fa = *(float4*)&xsT[k * 128 + r0];
        float4 fb = *(float4*)&xsT[k * 128 + r0 + 4];
        float4 wa = *(float4*)&ws[k * 128 + c0];
        float4 wb = *(float4*)&ws[k * 128 + c0 + 64];
        float fr[8] = {fa.x, fa.y, fa.z, fa.w, fb.x, fb.y, fb.z, fb.w};
        float wc[8] = {wa.x, wa.y, wa.z, wa.w, wb.x, wb.y, wb.z, wb.w};
#pragma unroll
        for (int i = 0; i < 8; i++)
#pragma unroll
            for (int j = 0; j < 8; j++)
                acc[i][j] = fmaf(fr[i], wc[j], acc[i][j]);
    }
#pragma unroll
    for (int i = 0; i < 8; i++) {
        float4 o0, o1;
        o0.x = acc[i][0]; o0.y = acc[i][1]; o0.z = acc[i][2]; o0.w = acc[i][3];
        o1.x = acc[i][4]; o1.y = acc[i][5]; o1.z = acc[i][6]; o1.w = acc[i][7];
        *(float4*)(xout + (size_t)(p0 + r0 + i) * 128 + c0)      = o0;
        *(float4*)(xout + (size_t)(p0 + r0 + i) * 128 + c0 + 64) = o1;
    }
    float ps[8], pq[8];
#pragma unroll
    for (int j = 0; j < 8; j++) {
        float s = 0.f, q = 0.f;
#pragma unroll
        for (int i = 0; i < 8; i++) { s += acc[i][j]; q += acc[i][j] * acc[i][j]; }
        ps[j] = s; pq[j] = q;
    }
    int pg = tid >> 4;
#pragma unroll
    for (int j = 0; j < 4; j++) {
        sred[pg][c0 + j]      = ps[j];
        sred[pg][c0 + 64 + j] = ps[j + 4];
    }
    __syncthreads();
    if (tid < 128) {
        float s = 0.f;
#pragma unroll
        for (int g = 0; g < 16; g++) s += sred[g][tid];
        g_part[(size_t)tid * PBLK + bx] = s;
    }
    __syncthreads();
#pragma unroll
    for (int j = 0; j < 4; j++) {
        sred[pg][c0 + j]      = pq[j];
        sred[pg][c0 + 64 + j] = pq[j + 4];
    }
    __syncthreads();
    if (tid < 128) {
        float s = 0.f;
#pragma unroll
        for (int g = 0; g < 16; g++) s += sred[g][tid];
        g_part[(size_t)(128 + tid) * PBLK + bx] = s;
    }
}

// ---------------- final BN + ReLU + maxpool over K ----------------
__global__ void __launch_bounds__(128) maxpool_kernel(float* __restrict__ out2) {
    int g0 = blockIdx.x * 16, tid = threadIdx.x;
    float sc = g_scale[256 + tid], sh = g_shift[256 + tid];
    float m[16];
#pragma unroll
    for (int gi = 0; gi < 16; gi++) {
        size_t prow = (size_t)(g0 + gi) * 32;
        float mm = 0.f;
#pragma unroll 8
        for (int k = 0; k < 32; k++) {
            float v = g_x3[(prow + k) * 128 + tid];
            mm = fmaxf(mm, fmaxf(fmaf(v, sc, sh), 0.f));
        }
        m[gi] = mm;
    }
    int b = g0 >> 10;
    int s0 = g0 & 1023;
    float* dst = out2 + ((size_t)b * 128 + tid) * NPOINT + s0;
#pragma unroll
    for (int i = 0; i < 4; i++) {
        float4 o; o.x = m[i * 4]; o.y = m[i * 4 + 1]; o.z = m[i * 4 + 2]; o.w = m[i * 4 + 3];
        *(float4*)(dst + i * 4) = o;
    }
}

// ---------------- launch ----------------
extern "C" void kernel_launch(void* const* d_in, const int* in_sizes, int n_in,
                              void* d_out, int out_size) {
    const float* xyz = (const float*)d_in[0];
    const float* pts = (const float*)d_in[1];
    const float* W0 = (const float*)d_in[2];  const float* b0 = (const float*)d_in[3];
    const float* ga0 = (const float*)d_in[4]; const float* be0 = (const float*)d_in[5];
    const float* W1 = (const float*)d_in[6];  const float* b1 = (const float*)d_in[7];
    const float* ga1 = (const float*)d_in[8]; const float* be1 = (const float*)d_in[9];
    const float* W2 = (const float*)d_in[10]; const float* b2 = (const float*)d_in[11];
    const float* ga2 = (const float*)d_in[12]; const float* be2 = (const float*)d_in[13];
    float* out = (float*)d_out;
    float* out2 = out + (size_t)BATCH * 3 * NPOINT;

    float* d_x1; cudaGetSymbolAddress((void**)&d_x1, g_x1);
    float* d_x2; cudaGetSymbolAddress((void**)&d_x2, g_x2);
    float* d_x3; cudaGetSymbolAddress((void**)&d_x3, g_x3);

    const int smem_l1   = (68 * 128 + 68 * 64) * 4;    // 52224
    const int smem_m64  = (64 * 128 + 64 * 64) * 4;    // 49152
    const int smem_m128 = (64 * 128 + 64 * 128) * 4;   // 65536
    cudaFuncSetAttribute(l1_kernel,     cudaFuncAttributeMaxDynamicSharedMemorySize, smem_l1);
    cudaFuncSetAttribute(mlp64_kernel,  cudaFuncAttributeMaxDynamicSharedMemorySize, smem_m64);
    cudaFuncSetAttribute(mlp128_kernel, cudaFuncAttributeMaxDynamicSharedMemorySize, smem_m128);

    prep_kernel<<<dim3(64, 16), 256>>>(xyz, pts);
    fps_kernel<<<16, 256>>>(xyz, out);
    ballq_kernel<<<dim3(16, 16), 256>>>(xyz);

    l1_kernel<<<PBLK, 128, smem_l1>>>(W0, b0);
    fold_kernel<<<64, 256>>>(ga0, be0, 64, 0);

    mlp64_kernel<<<PBLK, 128, smem_m64>>>(d_x1, W1, b1, 0, d_x2);
    fold_kernel<<<64, 256>>>(ga1, be1, 64, 128);

    mlp128_kernel<<<PBLK, 256, smem_m128>>>(d_x2, W2, b2, 128, d_x3);
    fold_kernel<<<128, 256>>>(ga2, be2, 128, 256);

    maxpool_kernel<<<BATCH * NPOINT / 16, 128>>>(out2);
}